// round 9
// baseline (speedup 1.0000x reference)
#include <cuda_runtime.h>
#include <cuda_fp16.h>
#include <cstdint>
#include <math.h>

// ---------------- problem constants ----------------
constexpr int kB    = 2;
constexpr int kC    = 512;
constexpr int kHW   = 4096;
constexpr int kG    = 32;
constexpr int kCPG  = kC / kG;       // 16
constexpr float kEPS = 1e-6f;

// ---------------- scratch ----------------
__device__ __half g_hnt[(size_t)kB * kHW * kC];        // hn^T [b][p][c]        8 MB
__device__ __half g_qkt[(size_t)kB * kHW * 1024];      // q,k^T [b][p][0:1024] 16 MB
__device__ __half g_v  [(size_t)kB * kC * kHW];        // v [b][c][p]           8 MB
__device__ __half g_e  [(size_t)kB * kHW * kHW];       // exp(scores) fp16     64 MB
__device__ __half g_attt[(size_t)kB * kHW * kC];       // att^T [b][p][c]       8 MB
__device__ __half g_w16[1536 * 512 + 512 * 512];       // qkv_w + proj_w fp16
__device__ float  g_rowsum[(size_t)kB * kHW];          // softmax denominators

// ---------------- helpers ----------------
__device__ __forceinline__ uint32_t smem_u32(const void* p) {
    uint32_t a;
    asm("{ .reg .u64 t; cvta.to.shared.u64 t, %1; cvt.u32.u64 %0, t; }" : "=r"(a) : "l"(p));
    return a;
}
__device__ __forceinline__ void cpa16(uint32_t s, const __half* g) {
    asm volatile("cp.async.cg.shared.global [%0], [%1], 16;" :: "r"(s), "l"(g) : "memory");
}
#define CP_COMMIT() asm volatile("cp.async.commit_group;" ::: "memory")
#define CP_WAIT(n)  asm volatile("cp.async.wait_group %0;" :: "n"(n) : "memory")

// ---------------- weight fp16 conversion + rowsum zero ----------------
__global__ void convert_w_kernel(const float* __restrict__ qkv_w,
                                 const float* __restrict__ proj_w)
{
    const int n1 = 1536 * 512;
    const int n2 = 512 * 512;
    const int nr = kB * kHW;
    for (int i = blockIdx.x * blockDim.x + threadIdx.x; i < n1 + n2;
         i += gridDim.x * blockDim.x) {
        float v = (i < n1) ? qkv_w[i] : proj_w[i - n1];
        g_w16[i] = __float2half(v);
    }
    for (int i = blockIdx.x * blockDim.x + threadIdx.x; i < nr;
         i += gridDim.x * blockDim.x)
        g_rowsum[i] = 0.f;
}

// ---------------- GroupNorm (writes hn^T [p, c], fp16) ----------------
__global__ void groupnorm_kernel(const float* __restrict__ x,
                                 const float* __restrict__ gamma,
                                 const float* __restrict__ beta,
                                 __half* __restrict__ hnt)
{
    const int bg = blockIdx.x;
    const int b  = bg / kG;
    const int g  = bg % kG;
    const size_t xbase = ((size_t)b * kC + (size_t)g * kCPG) * kHW;
    const float* xp = x + xbase;

    const int NELEM = kCPG * kHW;  // 65536
    float s = 0.f, ss = 0.f;
    for (int i = threadIdx.x; i < NELEM; i += blockDim.x) {
        float v = xp[i];
        s += v; ss += v * v;
    }
    __shared__ float sha[8], shb[8];
    for (int o = 16; o; o >>= 1) {
        s  += __shfl_xor_sync(0xffffffffu, s,  o);
        ss += __shfl_xor_sync(0xffffffffu, ss, o);
    }
    int w = threadIdx.x >> 5;
    if ((threadIdx.x & 31) == 0) { sha[w] = s; shb[w] = ss; }
    __syncthreads();
    if (threadIdx.x < 32) {
        s  = (threadIdx.x < 8) ? sha[threadIdx.x] : 0.f;
        ss = (threadIdx.x < 8) ? shb[threadIdx.x] : 0.f;
        for (int o = 4; o; o >>= 1) {
            s  += __shfl_xor_sync(0xffffffffu, s,  o);
            ss += __shfl_xor_sync(0xffffffffu, ss, o);
        }
        if (threadIdx.x == 0) { sha[0] = s; shb[0] = ss; }
    }
    __syncthreads();
    const float mean = sha[0] * (1.f / NELEM);
    const float var  = shb[0] * (1.f / NELEM) - mean * mean;
    const float rstd = rsqrtf(var + kEPS);

    __half* hb = hnt + (size_t)b * kHW * kC;
    for (int i = threadIdx.x; i < NELEM; i += blockDim.x) {
        int cl = i & 15, p = i >> 4;
        int ch = g * kCPG + cl;
        float v = (x[((size_t)b * kC + ch) * kHW + p] - mean) * rstd;
        hb[(size_t)p * kC + ch] = __float2half(v * gamma[ch] + beta[ch]);
    }
}

// ---------------- fp16 mma.sync GEMM 128x256x32, warp tile 64x64 ----------------
// D[m,n] = f( alpha * sum_k A[m,k]*B[n,k] )
// MODE 0: fp32 out + bias_m + residual
// MODE 1: fp16 out + optional bias_m / bias_n
// MODE 2: fp16 out = exp(alpha*acc), atomicAdd row sums into rowsum[z*M + m]
// MODE 3: fp16 out = acc / rowsum[z*M + m]
// A,B K-major fp16. M mult of 128, N mult of 256, K mult of 32. gridDim.z = batch.

#define MMA_F16(d, a, b) \
    asm volatile("mma.sync.aligned.m16n8k16.row.col.f32.f16.f16.f32 " \
        "{%0,%1,%2,%3},{%4,%5,%6,%7},{%8,%9},{%0,%1,%2,%3};" \
        : "+f"((d)[0]), "+f"((d)[1]), "+f"((d)[2]), "+f"((d)[3]) \
        : "r"((a)[0]), "r"((a)[1]), "r"((a)[2]), "r"((a)[3]), \
          "r"((b)[0]), "r"((b)[1]))

constexpr int kNS       = 4;
constexpr int kStrideH  = 40;                       // halves per smem row (80B)
constexpr int kATileH   = 128 * kStrideH;           // 5120 halves
constexpr int kBTileH   = 256 * kStrideH;           // 10240 halves
constexpr int kStageB   = (kATileH + kBTileH) * 2;  // 30720 bytes
constexpr int kSmemB    = kNS * kStageB;            // 122880

template<int MODE>
__global__ __launch_bounds__(256, 1) void gemm_h(
    const __half* __restrict__ Ap, const __half* __restrict__ Bp, void* __restrict__ Cv,
    int M, int N, int K, int lda, int ldb, int ldc,
    size_t sA, size_t sB, size_t sC,
    const float* __restrict__ bias_m, const float* __restrict__ bias_n,
    float alpha, const float* __restrict__ residual, size_t sRes,
    float* __restrict__ rowsum)
{
    extern __shared__ __align__(16) __half sm[];
    const int tid  = threadIdx.x;
    const int lane = tid & 31;
    const int wid  = tid >> 5;
    const int wm   = wid >> 2;          // 0..1  (64-row slab)
    const int wn   = wid & 3;           // 0..3  (64-col slab)
    const int g    = lane >> 2;         // 0..7
    const int t4   = lane & 3;          // 0..3
    const int bm = blockIdx.y * 128;
    const int bn = blockIdx.x * 256;
    const int z  = blockIdx.z;

    Ap += (size_t)z * sA;
    Bp += (size_t)z * sB;

    const uint32_t smBase = smem_u32(sm);
    const int lr = tid >> 2;            // 0..63
    const int lj = tid & 3;             // 16B chunk within 32-half row

    auto issue = [&](int stage, int k0) {
        const uint32_t sb = smBase + stage * kStageB;
        #pragma unroll
        for (int i = 0; i < 2; i++) {   // A: 128 rows
            int r = lr + (i << 6);
            uint32_t so = (uint32_t)((r * kStrideH + (lj << 3)) * 2);
            cpa16(sb + so, Ap + (size_t)(bm + r) * lda + k0 + (lj << 3));
        }
        #pragma unroll
        for (int i = 0; i < 4; i++) {   // B: 256 rows
            int r = lr + (i << 6);
            uint32_t so = (uint32_t)((r * kStrideH + (lj << 3)) * 2);
            cpa16(sb + (uint32_t)(kATileH * 2) + so,
                  Bp + (size_t)(bn + r) * ldb + k0 + (lj << 3));
        }
    };

    // ldmatrix per-lane byte offsets within a tile
    const uint32_t aLaneOff = (uint32_t)(((wm * 64 + (lane & 15)) * kStrideH
                                          + (((lane >> 4) & 1) << 3)) * 2);
    // B x4: lanes 0-7 rows p*16+0..7 kLow | 8-15 same rows kHigh | 16-23 rows+8 kLow | 24-31 rows+8 kHigh
    const uint32_t bLaneOff = (uint32_t)(((wn * 64 + (lane & 7) + (((lane >> 4) & 1) << 3)) * kStrideH
                                          + (((lane >> 3) & 1) << 3)) * 2);

    float acc[4][8][4];
    #pragma unroll
    for (int a = 0; a < 4; a++)
        #pragma unroll
        for (int b = 0; b < 8; b++)
            #pragma unroll
            for (int c = 0; c < 4; c++) acc[a][b][c] = 0.f;

    const int nch = K >> 5;

    #pragma unroll
    for (int s = 0; s < kNS - 1; s++) { issue(s, s << 5); CP_COMMIT(); }

    int cur = 0;
    for (int ch = 0; ch < nch; ch++) {
        CP_WAIT(kNS - 2);
        __syncthreads();

        const uint32_t aB = smBase + cur * kStageB + aLaneOff;
        const uint32_t bB = smBase + cur * kStageB + (uint32_t)(kATileH * 2) + bLaneOff;
        #pragma unroll
        for (int s = 0; s < 2; s++) {
            const uint32_t kOfs = (uint32_t)(s << 5);   // 16 halves = 32B
            uint32_t aF[4][4], bF[8][2];
            #pragma unroll
            for (int mt = 0; mt < 4; mt++) {
                asm volatile("ldmatrix.sync.aligned.m8n8.x4.shared.b16 {%0,%1,%2,%3}, [%4];"
                    : "=r"(aF[mt][0]), "=r"(aF[mt][1]), "=r"(aF[mt][2]), "=r"(aF[mt][3])
                    : "r"(aB + (uint32_t)(mt * 16 * kStrideH * 2) + kOfs));
            }
            #pragma unroll
            for (int p = 0; p < 4; p++) {   // each x4 serves 2 n-tiles
                asm volatile("ldmatrix.sync.aligned.m8n8.x4.shared.b16 {%0,%1,%2,%3}, [%4];"
                    : "=r"(bF[2*p][0]), "=r"(bF[2*p][1]), "=r"(bF[2*p+1][0]), "=r"(bF[2*p+1][1])
                    : "r"(bB + (uint32_t)(p * 16 * kStrideH * 2) + kOfs));
            }
            #pragma unroll
            for (int mt = 0; mt < 4; mt++)
                #pragma unroll
                for (int nt = 0; nt < 8; nt++)
                    MMA_F16(acc[mt][nt], aF[mt], bF[nt]);
        }

        const int nx = ch + kNS - 1;
        if (nx < nch) issue(nx % kNS, nx << 5);
        CP_COMMIT();                     // empty group in the tail keeps wait-count exact
        if (++cur == kNS) cur = 0;
    }

    // ---- epilogue ----
    __syncthreads();   // safe smem reuse
    float* rs = reinterpret_cast<float*>(sm);
    if (MODE == 2) {
        if (tid < 128) rs[tid] = 0.f;
        __syncthreads();
    }

    #pragma unroll
    for (int mt = 0; mt < 4; mt++) {
        const int r0l = wm * 64 + mt * 16 + g;
        const int r1l = r0l + 8;
        const int r0 = bm + r0l;
        const int r1 = bm + r1l;
        float bm0 = 0.f, bm1 = 0.f;
        if (MODE <= 1 && bias_m) { bm0 = bias_m[r0]; bm1 = bias_m[r1]; }
        float inv0 = 1.f, inv1 = 1.f;
        if (MODE == 3) {
            inv0 = 1.f / rowsum[(size_t)z * M + r0];
            inv1 = 1.f / rowsum[(size_t)z * M + r1];
        }
        float sum0 = 0.f, sum1 = 0.f;
        #pragma unroll
        for (int nt = 0; nt < 8; nt++) {
            const int c = bn + wn * 64 + nt * 8 + t4 * 2;
            float bn0 = 0.f, bn1 = 0.f;
            if (MODE <= 1 && bias_n) { bn0 = bias_n[c]; bn1 = bias_n[c + 1]; }
            float o00 = acc[mt][nt][0] * alpha + bm0 + bn0;
            float o01 = acc[mt][nt][1] * alpha + bm0 + bn1;
            float o10 = acc[mt][nt][2] * alpha + bm1 + bn0;
            float o11 = acc[mt][nt][3] * alpha + bm1 + bn1;
            const size_t off0 = (size_t)r0 * ldc + c;
            const size_t off1 = (size_t)r1 * ldc + c;
            if (MODE == 0) {
                float* Cc = (float*)Cv + (size_t)z * sC;
                if (residual) {
                    const float* res = residual + (size_t)z * sRes;
                    float2 q0 = *reinterpret_cast<const float2*>(res + off0);
                    float2 q1 = *reinterpret_cast<const float2*>(res + off1);
                    o00 += q0.x; o01 += q0.y; o10 += q1.x; o11 += q1.y;
                }
                *reinterpret_cast<float2*>(Cc + off0) = make_float2(o00, o01);
                *reinterpret_cast<float2*>(Cc + off1) = make_float2(o10, o11);
            } else {
                __half* Cc = (__half*)Cv + (size_t)z * sC;
                if (MODE == 2) {
                    o00 = __expf(o00); o01 = __expf(o01);
                    o10 = __expf(o10); o11 = __expf(o11);
                    sum0 += o00 + o01; sum1 += o10 + o11;
                } else if (MODE == 3) {
                    o00 *= inv0; o01 *= inv0; o10 *= inv1; o11 *= inv1;
                }
                *reinterpret_cast<__half2*>(Cc + off0) = __floats2half2_rn(o00, o01);
                *reinterpret_cast<__half2*>(Cc + off1) = __floats2half2_rn(o10, o11);
            }
        }
        if (MODE == 2) {
            atomicAdd(&rs[r0l], sum0);
            atomicAdd(&rs[r1l], sum1);
        }
    }
    if (MODE == 2) {
        __syncthreads();
        if (tid < 128)
            atomicAdd(&rowsum[(size_t)z * M + bm + tid], rs[tid]);
    }
}

// ---------------- launch ----------------
extern "C" void kernel_launch(void* const* d_in, const int* in_sizes, int n_in,
                              void* d_out, int out_size)
{
    const float* x      = (const float*)d_in[0];
    const float* gamma  = (const float*)d_in[1];
    const float* beta   = (const float*)d_in[2];
    const float* qkv_w  = (const float*)d_in[3];
    const float* qkv_b  = (const float*)d_in[4];
    const float* proj_w = (const float*)d_in[5];
    const float* proj_b = (const float*)d_in[6];
    float* out = (float*)d_out;

    __half *hnt, *qkt, *v, *E, *attt, *w16;
    float *rowsum;
    cudaGetSymbolAddress((void**)&hnt, g_hnt);
    cudaGetSymbolAddress((void**)&qkt, g_qkt);
    cudaGetSymbolAddress((void**)&v, g_v);
    cudaGetSymbolAddress((void**)&E, g_e);
    cudaGetSymbolAddress((void**)&attt, g_attt);
    cudaGetSymbolAddress((void**)&w16, g_w16);
    cudaGetSymbolAddress((void**)&rowsum, g_rowsum);

    const __half* w16_qk   = w16;                       // rows [0,1024) of qkv_w
    const __half* w16_v    = w16 + (size_t)1024 * kC;   // rows [1024,1536)
    const __half* w16_proj = w16 + (size_t)1536 * kC;   // proj_w

    cudaFuncSetAttribute(gemm_h<0>, cudaFuncAttributeMaxDynamicSharedMemorySize, kSmemB);
    cudaFuncSetAttribute(gemm_h<1>, cudaFuncAttributeMaxDynamicSharedMemorySize, kSmemB);
    cudaFuncSetAttribute(gemm_h<2>, cudaFuncAttributeMaxDynamicSharedMemorySize, kSmemB);
    cudaFuncSetAttribute(gemm_h<3>, cudaFuncAttributeMaxDynamicSharedMemorySize, kSmemB);

    const float scale = 0.044194173824159216f;  // 512^-0.5

    convert_w_kernel<<<256, 256>>>(qkv_w, proj_w);
    groupnorm_kernel<<<kB * kG, 256>>>(x, gamma, beta, hnt);

    const size_t sHnt = (size_t)kHW * kC;
    const size_t sQkt = (size_t)kHW * 1024;
    const size_t sV   = (size_t)kC * kHW;
    const size_t sE   = (size_t)kHW * kHW;
    const size_t sAtt = (size_t)kHW * kC;
    const size_t sOut = (size_t)kC * kHW;

    // qk^T[p,o] = sum_c hn^T[p,c] * Wqk[o,c] + qkv_b[o]
    gemm_h<1><<<dim3(4, 32, kB), 256, kSmemB>>>(
        hnt, w16_qk, qkt, kHW, 1024, kC, kC, kC, 1024,
        sHnt, 0, sQkt, nullptr, qkv_b, 1.f, nullptr, 0, nullptr);

    // v[c',p] = sum_c Wv[c',c] * hn^T[p,c] + qkv_b[1024+c']
    gemm_h<1><<<dim3(16, 4, kB), 256, kSmemB>>>(
        w16_v, hnt, v, kC, kHW, kC, kC, kC, kHW,
        0, sHnt, sV, qkv_b + 1024, nullptr, 1.f, nullptr, 0, nullptr);

    // E[i,j] = exp(scale * sum_c q^T[i,c] * k^T[j,c]);  rowsum[i] += row partials
    gemm_h<2><<<dim3(16, 32, kB), 256, kSmemB>>>(
        qkt, qkt + 512, E, kHW, kHW, kC, 1024, 1024, kHW,
        sQkt, sQkt, sE, nullptr, nullptr, scale, nullptr, 0, rowsum);

    // att^T[i,c'] = (sum_j E[i,j] * v[c',j]) / rowsum[i]
    gemm_h<3><<<dim3(2, 32, kB), 256, kSmemB>>>(
        E, v, attt, kHW, kC, kHW, kHW, kHW, kC,
        sE, sV, sAtt, nullptr, nullptr, 1.f, nullptr, 0, rowsum);

    // out[o,p] = sum_c Pw[o,c] * att^T[p,c] + proj_b[o] + x[o,p]
    gemm_h<0><<<dim3(16, 4, kB), 256, kSmemB>>>(
        w16_proj, attt, out, kC, kHW, kC, kC, kC, kHW,
        0, sAtt, sOut, proj_b, nullptr, 1.f, x, sOut, nullptr);
}

// round 10
// speedup vs baseline: 1.3781x; 1.3781x over previous
#include <cuda_runtime.h>
#include <cuda_fp16.h>
#include <cstdint>
#include <math.h>

// ---------------- problem constants ----------------
constexpr int kB    = 2;
constexpr int kC    = 512;
constexpr int kHW   = 4096;
constexpr int kG    = 32;
constexpr int kCPG  = kC / kG;       // 16
constexpr float kEPS = 1e-6f;

// ---------------- scratch ----------------
__device__ __half g_hnt[(size_t)kB * kHW * kC];        // hn^T [b][p][c]        8 MB
__device__ __half g_qkt[(size_t)kB * kHW * 1024];      // q,k^T [b][p][0:1024] 16 MB
__device__ __half g_v  [(size_t)kB * kC * kHW];        // v [b][c][p]           8 MB
__device__ __half g_e  [(size_t)kB * kHW * kHW];       // exp(scores) fp16     64 MB
__device__ __half g_attt[(size_t)kB * kHW * kC];       // att^T [b][p][c]       8 MB
__device__ __half g_w16[1536 * 512 + 512 * 512];       // qkv_w + proj_w fp16
__device__ float  g_rowsum[(size_t)kB * kHW];          // softmax denominators

// ---------------- helpers ----------------
__device__ __forceinline__ uint32_t smem_u32(const void* p) {
    uint32_t a;
    asm("{ .reg .u64 t; cvta.to.shared.u64 t, %1; cvt.u32.u64 %0, t; }" : "=r"(a) : "l"(p));
    return a;
}
__device__ __forceinline__ void cpa16(uint32_t s, const __half* g) {
    asm volatile("cp.async.cg.shared.global [%0], [%1], 16;" :: "r"(s), "l"(g) : "memory");
}
#define CP_COMMIT() asm volatile("cp.async.commit_group;" ::: "memory")
#define CP_WAIT(n)  asm volatile("cp.async.wait_group %0;" :: "n"(n) : "memory")

// ---------------- weight fp16 conversion + rowsum zero ----------------
__global__ void convert_w_kernel(const float* __restrict__ qkv_w,
                                 const float* __restrict__ proj_w)
{
    const int n1 = 1536 * 512;
    const int n2 = 512 * 512;
    const int nr = kB * kHW;
    for (int i = blockIdx.x * blockDim.x + threadIdx.x; i < n1 + n2;
         i += gridDim.x * blockDim.x) {
        float v = (i < n1) ? qkv_w[i] : proj_w[i - n1];
        g_w16[i] = __float2half(v);
    }
    for (int i = blockIdx.x * blockDim.x + threadIdx.x; i < nr;
         i += gridDim.x * blockDim.x)
        g_rowsum[i] = 0.f;
}

// ---------------- GroupNorm (writes hn^T [p, c], fp16) ----------------
__global__ void groupnorm_kernel(const float* __restrict__ x,
                                 const float* __restrict__ gamma,
                                 const float* __restrict__ beta,
                                 __half* __restrict__ hnt)
{
    const int bg = blockIdx.x;
    const int b  = bg / kG;
    const int g  = bg % kG;
    const size_t xbase = ((size_t)b * kC + (size_t)g * kCPG) * kHW;
    const float* xp = x + xbase;

    const int NELEM = kCPG * kHW;  // 65536
    float s = 0.f, ss = 0.f;
    for (int i = threadIdx.x; i < NELEM; i += blockDim.x) {
        float v = xp[i];
        s += v; ss += v * v;
    }
    __shared__ float sha[8], shb[8];
    for (int o = 16; o; o >>= 1) {
        s  += __shfl_xor_sync(0xffffffffu, s,  o);
        ss += __shfl_xor_sync(0xffffffffu, ss, o);
    }
    int w = threadIdx.x >> 5;
    if ((threadIdx.x & 31) == 0) { sha[w] = s; shb[w] = ss; }
    __syncthreads();
    if (threadIdx.x < 32) {
        s  = (threadIdx.x < 8) ? sha[threadIdx.x] : 0.f;
        ss = (threadIdx.x < 8) ? shb[threadIdx.x] : 0.f;
        for (int o = 4; o; o >>= 1) {
            s  += __shfl_xor_sync(0xffffffffu, s,  o);
            ss += __shfl_xor_sync(0xffffffffu, ss, o);
        }
        if (threadIdx.x == 0) { sha[0] = s; shb[0] = ss; }
    }
    __syncthreads();
    const float mean = sha[0] * (1.f / NELEM);
    const float var  = shb[0] * (1.f / NELEM) - mean * mean;
    const float rstd = rsqrtf(var + kEPS);

    __half* hb = hnt + (size_t)b * kHW * kC;
    for (int i = threadIdx.x; i < NELEM; i += blockDim.x) {
        int cl = i & 15, p = i >> 4;
        int ch = g * kCPG + cl;
        float v = (x[((size_t)b * kC + ch) * kHW + p] - mean) * rstd;
        hb[(size_t)p * kC + ch] = __float2half(v * gamma[ch] + beta[ch]);
    }
}

// ---------------- fp16 mma.sync GEMM 128x128x32, warp tile 64x32 ----------------
// D[m,n] = f( alpha * sum_k A[m,k]*B[n,k] )
// MODE 0: fp32 out + bias_m + residual
// MODE 1: fp16 out + optional bias_m / bias_n
// MODE 2: fp16 out = exp(alpha*acc), atomicAdd row sums into rowsum[z*M + m]
// MODE 3: fp16 out = acc / rowsum[z*M + m]
// A,B K-major fp16. M,N mult of 128, K mult of 32. gridDim.z = batch.

#define MMA_F16(d, a, b) \
    asm volatile("mma.sync.aligned.m16n8k16.row.col.f32.f16.f16.f32 " \
        "{%0,%1,%2,%3},{%4,%5,%6,%7},{%8,%9},{%0,%1,%2,%3};" \
        : "+f"((d)[0]), "+f"((d)[1]), "+f"((d)[2]), "+f"((d)[3]) \
        : "r"((a)[0]), "r"((a)[1]), "r"((a)[2]), "r"((a)[3]), \
          "r"((b)[0]), "r"((b)[1]))

constexpr int kNS       = 5;
constexpr int kStrideH  = 40;                      // halves per smem row (80B)
constexpr int kTileHalf = 128 * kStrideH;          // 5120 halves per matrix tile
constexpr int kStageB   = kTileHalf * 2 * 2;       // A+B bytes per stage = 20480
constexpr int kSmemB    = kNS * kStageB;           // 102400

template<int MODE>
__global__ __launch_bounds__(256, 2) void gemm_h(
    const __half* __restrict__ Ap, const __half* __restrict__ Bp, void* __restrict__ Cv,
    int M, int N, int K, int lda, int ldb, int ldc,
    size_t sA, size_t sB, size_t sC,
    const float* __restrict__ bias_m, const float* __restrict__ bias_n,
    float alpha, const float* __restrict__ residual, size_t sRes,
    float* __restrict__ rowsum)
{
    extern __shared__ __align__(16) __half sm[];
    const int tid  = threadIdx.x;
    const int lane = tid & 31;
    const int wid  = tid >> 5;
    const int wm   = wid >> 2;          // 0..1
    const int wn   = wid & 3;           // 0..3
    const int g    = lane >> 2;         // 0..7
    const int t4   = lane & 3;          // 0..3
    const int bm = blockIdx.y * 128;
    const int bn = blockIdx.x * 128;
    const int z  = blockIdx.z;

    Ap += (size_t)z * sA;
    Bp += (size_t)z * sB;

    const uint32_t smBase = smem_u32(sm);
    const int lr = tid >> 2;
    const int lj = tid & 3;

    auto issue = [&](int stage, int k0) {
        const uint32_t sb = smBase + stage * kStageB;
        #pragma unroll
        for (int i = 0; i < 2; i++) {
            int r = lr + (i << 6);
            uint32_t so = (uint32_t)((r * kStrideH + (lj << 3)) * 2);
            cpa16(sb + so, Ap + (size_t)(bm + r) * lda + k0 + (lj << 3));
            cpa16(sb + (uint32_t)(kTileHalf * 2) + so,
                  Bp + (size_t)(bn + r) * ldb + k0 + (lj << 3));
        }
    };

    // ldmatrix per-lane byte offsets within a tile
    const uint32_t aLaneOff = (uint32_t)(((wm * 64 + (lane & 15)) * kStrideH
                                          + (((lane >> 4) & 1) << 3)) * 2);
    // B x4 pairs: row = wn*32 + (lane&7) + ((lane>>4)&1)*8, kchunk = (lane>>3)&1
    const uint32_t bLaneOff = (uint32_t)(((wn * 32 + (lane & 7) + (((lane >> 4) & 1) << 3)) * kStrideH
                                          + (((lane >> 3) & 1) << 3)) * 2);

    float acc[4][4][4];
    #pragma unroll
    for (int a = 0; a < 4; a++)
        #pragma unroll
        for (int b = 0; b < 4; b++)
            #pragma unroll
            for (int c = 0; c < 4; c++) acc[a][b][c] = 0.f;

    const int nch = K >> 5;

    #pragma unroll
    for (int s = 0; s < kNS - 1; s++) { issue(s, s << 5); CP_COMMIT(); }

    int cur = 0;
    for (int ch = 0; ch < nch; ch++) {
        CP_WAIT(kNS - 2);
        __syncthreads();

        const uint32_t aB = smBase + cur * kStageB + aLaneOff;
        const uint32_t bB = smBase + cur * kStageB + (uint32_t)(kTileHalf * 2) + bLaneOff;
        #pragma unroll
        for (int s = 0; s < 2; s++) {
            const uint32_t kOfs = (uint32_t)(s << 5);   // 16 halves = 32B
            uint32_t aF[4][4], bF[4][2];
            #pragma unroll
            for (int mt = 0; mt < 4; mt++) {
                asm volatile("ldmatrix.sync.aligned.m8n8.x4.shared.b16 {%0,%1,%2,%3}, [%4];"
                    : "=r"(aF[mt][0]), "=r"(aF[mt][1]), "=r"(aF[mt][2]), "=r"(aF[mt][3])
                    : "r"(aB + (uint32_t)(mt * 16 * kStrideH * 2) + kOfs));
            }
            #pragma unroll
            for (int p = 0; p < 2; p++) {   // each x4 serves 2 n-tiles
                asm volatile("ldmatrix.sync.aligned.m8n8.x4.shared.b16 {%0,%1,%2,%3}, [%4];"
                    : "=r"(bF[2*p][0]), "=r"(bF[2*p][1]), "=r"(bF[2*p+1][0]), "=r"(bF[2*p+1][1])
                    : "r"(bB + (uint32_t)(p * 16 * kStrideH * 2) + kOfs));
            }
            #pragma unroll
            for (int mt = 0; mt < 4; mt++)
                #pragma unroll
                for (int nt = 0; nt < 4; nt++)
                    MMA_F16(acc[mt][nt], aF[mt], bF[nt]);
        }

        const int nx = ch + kNS - 1;
        if (nx < nch) issue(nx % kNS, nx << 5);
        CP_COMMIT();                     // always commit: keeps wait-group count exact
        if (++cur == kNS) cur = 0;
    }

    // ---- epilogue ----
    __syncthreads();   // safe smem reuse
    float* rs = reinterpret_cast<float*>(sm);
    if (MODE == 2) {
        if (tid < 128) rs[tid] = 0.f;
        __syncthreads();
    }

    #pragma unroll
    for (int mt = 0; mt < 4; mt++) {
        const int r0l = wm * 64 + mt * 16 + g;
        const int r1l = r0l + 8;
        const int r0 = bm + r0l;
        const int r1 = bm + r1l;
        float bm0 = 0.f, bm1 = 0.f;
        if (MODE <= 1 && bias_m) { bm0 = bias_m[r0]; bm1 = bias_m[r1]; }
        float inv0 = 1.f, inv1 = 1.f;
        if (MODE == 3) {
            inv0 = 1.f / rowsum[(size_t)z * M + r0];
            inv1 = 1.f / rowsum[(size_t)z * M + r1];
        }
        float sum0 = 0.f, sum1 = 0.f;
        #pragma unroll
        for (int nt = 0; nt < 4; nt++) {
            const int c = bn + wn * 32 + nt * 8 + t4 * 2;
            float bn0 = 0.f, bn1 = 0.f;
            if (MODE <= 1 && bias_n) { bn0 = bias_n[c]; bn1 = bias_n[c + 1]; }
            float o00 = acc[mt][nt][0] * alpha + bm0 + bn0;
            float o01 = acc[mt][nt][1] * alpha + bm0 + bn1;
            float o10 = acc[mt][nt][2] * alpha + bm1 + bn0;
            float o11 = acc[mt][nt][3] * alpha + bm1 + bn1;
            const size_t off0 = (size_t)r0 * ldc + c;
            const size_t off1 = (size_t)r1 * ldc + c;
            if (MODE == 0) {
                float* Cc = (float*)Cv + (size_t)z * sC;
                if (residual) {
                    const float* res = residual + (size_t)z * sRes;
                    float2 q0 = *reinterpret_cast<const float2*>(res + off0);
                    float2 q1 = *reinterpret_cast<const float2*>(res + off1);
                    o00 += q0.x; o01 += q0.y; o10 += q1.x; o11 += q1.y;
                }
                *reinterpret_cast<float2*>(Cc + off0) = make_float2(o00, o01);
                *reinterpret_cast<float2*>(Cc + off1) = make_float2(o10, o11);
            } else {
                __half* Cc = (__half*)Cv + (size_t)z * sC;
                if (MODE == 2) {
                    o00 = __expf(o00); o01 = __expf(o01);
                    o10 = __expf(o10); o11 = __expf(o11);
                    sum0 += o00 + o01; sum1 += o10 + o11;
                } else if (MODE == 3) {
                    o00 *= inv0; o01 *= inv0; o10 *= inv1; o11 *= inv1;
                }
                *reinterpret_cast<__half2*>(Cc + off0) = __floats2half2_rn(o00, o01);
                *reinterpret_cast<__half2*>(Cc + off1) = __floats2half2_rn(o10, o11);
            }
        }
        if (MODE == 2) {
            atomicAdd(&rs[r0l], sum0);
            atomicAdd(&rs[r1l], sum1);
        }
    }
    if (MODE == 2) {
        __syncthreads();
        if (tid < 128)
            atomicAdd(&rowsum[(size_t)z * M + bm + tid], rs[tid]);
    }
}

// ---------------- launch ----------------
extern "C" void kernel_launch(void* const* d_in, const int* in_sizes, int n_in,
                              void* d_out, int out_size)
{
    const float* x      = (const float*)d_in[0];
    const float* gamma  = (const float*)d_in[1];
    const float* beta   = (const float*)d_in[2];
    const float* qkv_w  = (const float*)d_in[3];
    const float* qkv_b  = (const float*)d_in[4];
    const float* proj_w = (const float*)d_in[5];
    const float* proj_b = (const float*)d_in[6];
    float* out = (float*)d_out;

    __half *hnt, *qkt, *v, *E, *attt, *w16;
    float *rowsum;
    cudaGetSymbolAddress((void**)&hnt, g_hnt);
    cudaGetSymbolAddress((void**)&qkt, g_qkt);
    cudaGetSymbolAddress((void**)&v, g_v);
    cudaGetSymbolAddress((void**)&E, g_e);
    cudaGetSymbolAddress((void**)&attt, g_attt);
    cudaGetSymbolAddress((void**)&w16, g_w16);
    cudaGetSymbolAddress((void**)&rowsum, g_rowsum);

    const __half* w16_qk   = w16;                       // rows [0,1024) of qkv_w
    const __half* w16_v    = w16 + (size_t)1024 * kC;   // rows [1024,1536)
    const __half* w16_proj = w16 + (size_t)1536 * kC;   // proj_w

    cudaFuncSetAttribute(gemm_h<0>, cudaFuncAttributeMaxDynamicSharedMemorySize, kSmemB);
    cudaFuncSetAttribute(gemm_h<1>, cudaFuncAttributeMaxDynamicSharedMemorySize, kSmemB);
    cudaFuncSetAttribute(gemm_h<2>, cudaFuncAttributeMaxDynamicSharedMemorySize, kSmemB);
    cudaFuncSetAttribute(gemm_h<3>, cudaFuncAttributeMaxDynamicSharedMemorySize, kSmemB);

    const float scale = 0.044194173824159216f;  // 512^-0.5

    convert_w_kernel<<<256, 256>>>(qkv_w, proj_w);
    groupnorm_kernel<<<kB * kG, 256>>>(x, gamma, beta, hnt);

    const size_t sHnt = (size_t)kHW * kC;
    const size_t sQkt = (size_t)kHW * 1024;
    const size_t sV   = (size_t)kC * kHW;
    const size_t sE   = (size_t)kHW * kHW;
    const size_t sAtt = (size_t)kHW * kC;
    const size_t sOut = (size_t)kC * kHW;

    // qk^T[p,o] = sum_c hn^T[p,c] * Wqk[o,c] + qkv_b[o]
    gemm_h<1><<<dim3(8, 32, kB), 256, kSmemB>>>(
        hnt, w16_qk, qkt, kHW, 1024, kC, kC, kC, 1024,
        sHnt, 0, sQkt, nullptr, qkv_b, 1.f, nullptr, 0, nullptr);

    // v[c',p] = sum_c Wv[c',c] * hn^T[p,c] + qkv_b[1024+c']
    gemm_h<1><<<dim3(32, 4, kB), 256, kSmemB>>>(
        w16_v, hnt, v, kC, kHW, kC, kC, kC, kHW,
        0, sHnt, sV, qkv_b + 1024, nullptr, 1.f, nullptr, 0, nullptr);

    // E[i,j] = exp(scale * sum_c q^T[i,c] * k^T[j,c]);  rowsum[i] += row partials
    gemm_h<2><<<dim3(32, 32, kB), 256, kSmemB>>>(
        qkt, qkt + 512, E, kHW, kHW, kC, 1024, 1024, kHW,
        sQkt, sQkt, sE, nullptr, nullptr, scale, nullptr, 0, rowsum);

    // att^T[i,c'] = (sum_j E[i,j] * v[c',j]) / rowsum[i]
    gemm_h<3><<<dim3(4, 32, kB), 256, kSmemB>>>(
        E, v, attt, kHW, kC, kHW, kHW, kHW, kC,
        sE, sV, sAtt, nullptr, nullptr, 1.f, nullptr, 0, rowsum);

    // out[o,p] = sum_c Pw[o,c] * att^T[p,c] + proj_b[o] + x[o,p]
    gemm_h<0><<<dim3(32, 4, kB), 256, kSmemB>>>(
        w16_proj, attt, out, kC, kHW, kC, kC, kC, kHW,
        0, sAtt, sOut, proj_b, nullptr, 1.f, x, sOut, nullptr);
}

// round 12
// speedup vs baseline: 1.4610x; 1.0602x over previous
#include <cuda_runtime.h>
#include <cuda_fp16.h>
#include <cstdint>
#include <math.h>

// ---------------- problem constants ----------------
constexpr int kB    = 2;
constexpr int kC    = 512;
constexpr int kHW   = 4096;
constexpr int kG    = 32;
constexpr int kCPG  = kC / kG;       // 16
constexpr float kEPS = 1e-6f;

// ---------------- scratch ----------------
__device__ __half g_hnt[(size_t)kB * kHW * kC];        // hn^T [b][p][c]        8 MB
__device__ __half g_qkt[(size_t)kB * kHW * 1024];      // q,k^T [b][p][0:1024] 16 MB
__device__ __half g_v  [(size_t)kB * kC * kHW];        // v [b][c][p]           8 MB
__device__ __half g_e  [(size_t)kB * kHW * kHW];       // exp(scores) fp16     64 MB
__device__ __half g_attt[(size_t)kB * kHW * kC];       // att^T [b][p][c]      8 MB
__device__ __half g_w16[1536 * 512 + 512 * 512];       // qkv_w + proj_w fp16
__device__ float  g_rowsum[(size_t)kB * kHW];          // softmax denominators

// ---------------- helpers ----------------
__device__ __forceinline__ uint32_t smem_u32(const void* p) {
    uint32_t a;
    asm("{ .reg .u64 t; cvta.to.shared.u64 t, %1; cvt.u32.u64 %0, t; }" : "=r"(a) : "l"(p));
    return a;
}
__device__ __forceinline__ void cpa16(uint32_t s, const __half* g) {
    asm volatile("cp.async.cg.shared.global [%0], [%1], 16;" :: "r"(s), "l"(g) : "memory");
}
#define CP_COMMIT() asm volatile("cp.async.commit_group;" ::: "memory")
#define CP_WAIT(n)  asm volatile("cp.async.wait_group %0;" :: "n"(n) : "memory")

// ---------------- weight fp16 conversion + rowsum zero ----------------
__global__ void convert_w_kernel(const float* __restrict__ qkv_w,
                                 const float* __restrict__ proj_w)
{
    const int n1 = 1536 * 512;
    const int n2 = 512 * 512;
    const int nr = kB * kHW;
    for (int i = blockIdx.x * blockDim.x + threadIdx.x; i < n1 + n2;
         i += gridDim.x * blockDim.x) {
        float v = (i < n1) ? qkv_w[i] : proj_w[i - n1];
        g_w16[i] = __float2half(v);
    }
    for (int i = blockIdx.x * blockDim.x + threadIdx.x; i < nr;
         i += gridDim.x * blockDim.x)
        g_rowsum[i] = 0.f;
}

// ---------------- GroupNorm (writes hn^T [p, c], fp16) ----------------
__global__ void groupnorm_kernel(const float* __restrict__ x,
                                 const float* __restrict__ gamma,
                                 const float* __restrict__ beta,
                                 __half* __restrict__ hnt)
{
    const int bg = blockIdx.x;
    const int b  = bg / kG;
    const int g  = bg % kG;
    const size_t xbase = ((size_t)b * kC + (size_t)g * kCPG) * kHW;
    const float* xp = x + xbase;

    const int NELEM = kCPG * kHW;  // 65536
    float s = 0.f, ss = 0.f;
    for (int i = threadIdx.x; i < NELEM; i += blockDim.x) {
        float v = xp[i];
        s += v; ss += v * v;
    }
    __shared__ float sha[8], shb[8];
    for (int o = 16; o; o >>= 1) {
        s  += __shfl_xor_sync(0xffffffffu, s,  o);
        ss += __shfl_xor_sync(0xffffffffu, ss, o);
    }
    int w = threadIdx.x >> 5;
    if ((threadIdx.x & 31) == 0) { sha[w] = s; shb[w] = ss; }
    __syncthreads();
    if (threadIdx.x < 32) {
        s  = (threadIdx.x < 8) ? sha[threadIdx.x] : 0.f;
        ss = (threadIdx.x < 8) ? shb[threadIdx.x] : 0.f;
        for (int o = 4; o; o >>= 1) {
            s  += __shfl_xor_sync(0xffffffffu, s,  o);
            ss += __shfl_xor_sync(0xffffffffu, ss, o);
        }
        if (threadIdx.x == 0) { sha[0] = s; shb[0] = ss; }
    }
    __syncthreads();
    const float mean = sha[0] * (1.f / NELEM);
    const float var  = shb[0] * (1.f / NELEM) - mean * mean;
    const float rstd = rsqrtf(var + kEPS);

    __half* hb = hnt + (size_t)b * kHW * kC;
    for (int i = threadIdx.x; i < NELEM; i += blockDim.x) {
        int cl = i & 15, p = i >> 4;
        int ch = g * kCPG + cl;
        float v = (x[((size_t)b * kC + ch) * kHW + p] - mean) * rstd;
        hb[(size_t)p * kC + ch] = __float2half(v * gamma[ch] + beta[ch]);
    }
}

// ---------------- fp16 mma.sync GEMM 128x128x64, warp tile 64x32 ----------------
// D[m,n] = f( alpha * sum_k A[m,k]*B[n,k] )
// MODE 0: fp32 out + bias_m + residual
// MODE 1: fp16 out + optional bias_m / bias_n
// MODE 2: fp16 out = exp(alpha*acc), atomicAdd row sums into rowsum[z*M + m]
// MODE 3: fp16 out = acc / rowsum[z*M + m]
// A,B K-major fp16. M,N mult of 128, K mult of 128. gridDim.z = batch.

#define MMA_F16(d, a, b) \
    asm volatile("mma.sync.aligned.m16n8k16.row.col.f32.f16.f16.f32 " \
        "{%0,%1,%2,%3},{%4,%5,%6,%7},{%8,%9},{%0,%1,%2,%3};" \
        : "+f"((d)[0]), "+f"((d)[1]), "+f"((d)[2]), "+f"((d)[3]) \
        : "r"((a)[0]), "r"((a)[1]), "r"((a)[2]), "r"((a)[3]), \
          "r"((b)[0]), "r"((b)[1]))

constexpr int kNS       = 3;
constexpr int kStrideH  = 72;                      // halves per smem row (144B): bank=(r+c)%8, conflict-free ldmatrix
constexpr int kTileHalf = 128 * kStrideH;          // 9216 halves per matrix tile
constexpr int kStageB   = kTileHalf * 2 * 2;       // A+B bytes per stage = 36864
constexpr int kSmemB    = kNS * kStageB;           // 110592 (2 CTAs/SM = 216 KB)

template<int MODE>
__global__ __launch_bounds__(256, 2) void gemm_h(
    const __half* __restrict__ Ap, const __half* __restrict__ Bp, void* __restrict__ Cv,
    int M, int N, int K, int lda, int ldb, int ldc,
    size_t sA, size_t sB, size_t sC,
    const float* __restrict__ bias_m, const float* __restrict__ bias_n,
    float alpha, const float* __restrict__ residual, size_t sRes,
    float* __restrict__ rowsum)
{
    extern __shared__ __align__(16) __half sm[];
    const int tid  = threadIdx.x;
    const int lane = tid & 31;
    const int wid  = tid >> 5;
    const int wm   = wid >> 2;          // 0..1
    const int wn   = wid & 3;           // 0..3
    const int g    = lane >> 2;         // 0..7
    const int t4   = lane & 3;          // 0..3
    const int bm = blockIdx.y * 128;
    const int bn = blockIdx.x * 128;
    const int z  = blockIdx.z;

    Ap += (size_t)z * sA;
    Bp += (size_t)z * sB;

    const uint32_t smBase = smem_u32(sm);
    const int lr = tid >> 3;            // 0..31 base row
    const int lj = tid & 7;             // 16B chunk (8 halves) within 64-half row

    auto issue = [&](int stage, int k0) {
        const uint32_t sb = smBase + stage * kStageB;
        #pragma unroll
        for (int i = 0; i < 4; i++) {   // 128 rows / 32
            int r = lr + (i << 5);
            uint32_t so = (uint32_t)((r * kStrideH + (lj << 3)) * 2);
            cpa16(sb + so, Ap + (size_t)(bm + r) * lda + k0 + (lj << 3));
            cpa16(sb + (uint32_t)(kTileHalf * 2) + so,
                  Bp + (size_t)(bn + r) * ldb + k0 + (lj << 3));
        }
    };

    // ldmatrix per-lane byte offsets within a tile
    const uint32_t aLaneOff = (uint32_t)(((wm * 64 + (lane & 15)) * kStrideH
                                          + (((lane >> 4) & 1) << 3)) * 2);
    const uint32_t bLaneOff = (uint32_t)(((wn * 32 + (lane & 7) + (((lane >> 4) & 1) << 3)) * kStrideH
                                          + (((lane >> 3) & 1) << 3)) * 2);

    float acc[4][4][4];
    #pragma unroll
    for (int a = 0; a < 4; a++)
        #pragma unroll
        for (int b = 0; b < 4; b++)
            #pragma unroll
            for (int c = 0; c < 4; c++) acc[a][b][c] = 0.f;

    const int nch = K >> 6;             // BK = 64

    issue(0, 0);  CP_COMMIT();
    issue(1, 64); CP_COMMIT();

    int cur = 0;
    for (int ch = 0; ch < nch; ch++) {
        CP_WAIT(1);                      // stage `cur` landed; newest stays in flight
        __syncthreads();                 // all warps done with stage being overwritten

        // issue 2 chunks ahead BEFORE compute so it overlaps this chunk's MMAs
        const int nx = ch + 2;
        if (nx < nch) issue(nx % kNS, nx << 6);
        CP_COMMIT();                     // always: keeps wait-group count exact

        const uint32_t aB = smBase + cur * kStageB + aLaneOff;
        const uint32_t bB = smBase + cur * kStageB + (uint32_t)(kTileHalf * 2) + bLaneOff;
        #pragma unroll
        for (int s = 0; s < 4; s++) {    // 4 x k16 per 64-chunk
            const uint32_t kOfs = (uint32_t)(s << 5);   // 16 halves = 32B
            uint32_t aF[4][4], bF[4][2];
            #pragma unroll
            for (int mt = 0; mt < 4; mt++) {
                asm volatile("ldmatrix.sync.aligned.m8n8.x4.shared.b16 {%0,%1,%2,%3}, [%4];"
                    : "=r"(aF[mt][0]), "=r"(aF[mt][1]), "=r"(aF[mt][2]), "=r"(aF[mt][3])
                    : "r"(aB + (uint32_t)(mt * 16 * kStrideH * 2) + kOfs));
            }
            #pragma unroll
            for (int p = 0; p < 2; p++) {   // each x4 serves 2 n-tiles
                asm volatile("ldmatrix.sync.aligned.m8n8.x4.shared.b16 {%0,%1,%2,%3}, [%4];"
                    : "=r"(bF[2*p][0]), "=r"(bF[2*p][1]), "=r"(bF[2*p+1][0]), "=r"(bF[2*p+1][1])
                    : "r"(bB + (uint32_t)(p * 16 * kStrideH * 2) + kOfs));
            }
            #pragma unroll
            for (int mt = 0; mt < 4; mt++)
                #pragma unroll
                for (int nt = 0; nt < 4; nt++)
                    MMA_F16(acc[mt][nt], aF[mt], bF[nt]);
        }

        if (++cur == kNS) cur = 0;
    }

    // ---- epilogue ----
    __syncthreads();   // safe smem reuse
    float* rs = reinterpret_cast<float*>(sm);
    if (MODE == 2) {
        if (tid < 128) rs[tid] = 0.f;
        __syncthreads();
    }

    #pragma unroll
    for (int mt = 0; mt < 4; mt++) {
        const int r0l = wm * 64 + mt * 16 + g;
        const int r1l = r0l + 8;
        const int r0 = bm + r0l;
        const int r1 = bm + r1l;
        float bm0 = 0.f, bm1 = 0.f;
        if (MODE <= 1 && bias_m) { bm0 = bias_m[r0]; bm1 = bias_m[r1]; }
        float inv0 = 1.f, inv1 = 1.f;
        if (MODE == 3) {
            inv0 = 1.f / rowsum[(size_t)z * M + r0];
            inv1 = 1.f / rowsum[(size_t)z * M + r1];
        }
        float sum0 = 0.f, sum1 = 0.f;
        #pragma unroll
        for (int nt = 0; nt < 4; nt++) {
            const int c = bn + wn * 32 + nt * 8 + t4 * 2;
            float bn0 = 0.f, bn1 = 0.f;
            if (MODE <= 1 && bias_n) { bn0 = bias_n[c]; bn1 = bias_n[c + 1]; }
            float o00 = acc[mt][nt][0] * alpha + bm0 + bn0;
            float o01 = acc[mt][nt][1] * alpha + bm0 + bn1;
            float o10 = acc[mt][nt][2] * alpha + bm1 + bn0;
            float o11 = acc[mt][nt][3] * alpha + bm1 + bn1;
            const size_t off0 = (size_t)r0 * ldc + c;
            const size_t off1 = (size_t)r1 * ldc + c;
            if (MODE == 0) {
                float* Cc = (float*)Cv + (size_t)z * sC;
                if (residual) {
                    const float* res = residual + (size_t)z * sRes;
                    float2 q0 = *reinterpret_cast<const float2*>(res + off0);
                    float2 q1 = *reinterpret_cast<const float2*>(res + off1);
                    o00 += q0.x; o01 += q0.y; o10 += q1.x; o11 += q1.y;
                }
                *reinterpret_cast<float2*>(Cc + off0) = make_float2(o00, o01);
                *reinterpret_cast<float2*>(Cc + off1) = make_float2(o10, o11);
            } else {
                __half* Cc = (__half*)Cv + (size_t)z * sC;
                if (MODE == 2) {
                    o00 = __expf(o00); o01 = __expf(o01);
                    o10 = __expf(o10); o11 = __expf(o11);
                    sum0 += o00 + o01; sum1 += o10 + o11;
                } else if (MODE == 3) {
                    o00 *= inv0; o01 *= inv0; o10 *= inv1; o11 *= inv1;
                }
                *reinterpret_cast<__half2*>(Cc + off0) = __floats2half2_rn(o00, o01);
                *reinterpret_cast<__half2*>(Cc + off1) = __floats2half2_rn(o10, o11);
            }
        }
        if (MODE == 2) {
            atomicAdd(&rs[r0l], sum0);
            atomicAdd(&rs[r1l], sum1);
        }
    }
    if (MODE == 2) {
        __syncthreads();
        if (tid < 128)
            atomicAdd(&rowsum[(size_t)z * M + bm + tid], rs[tid]);
    }
}

// ---------------- launch ----------------
extern "C" void kernel_launch(void* const* d_in, const int* in_sizes, int n_in,
                              void* d_out, int out_size)
{
    const float* x      = (const float*)d_in[0];
    const float* gamma  = (const float*)d_in[1];
    const float* beta   = (const float*)d_in[2];
    const float* qkv_w  = (const float*)d_in[3];
    const float* qkv_b  = (const float*)d_in[4];
    const float* proj_w = (const float*)d_in[5];
    const float* proj_b = (const float*)d_in[6];
    float* out = (float*)d_out;

    __half *hnt, *qkt, *v, *E, *attt, *w16;
    float *rowsum;
    cudaGetSymbolAddress((void**)&hnt, g_hnt);
    cudaGetSymbolAddress((void**)&qkt, g_qkt);
    cudaGetSymbolAddress((void**)&v, g_v);
    cudaGetSymbolAddress((void**)&E, g_e);
    cudaGetSymbolAddress((void**)&attt, g_attt);
    cudaGetSymbolAddress((void**)&w16, g_w16);
    cudaGetSymbolAddress((void**)&rowsum, g_rowsum);

    const __half* w16_qk   = w16;                       // rows [0,1024) of qkv_w
    const __half* w16_v    = w16 + (size_t)1024 * kC;   // rows [1024,1536)
    const __half* w16_proj = w16 + (size_t)1536 * kC;   // proj_w

    cudaFuncSetAttribute(gemm_h<0>, cudaFuncAttributeMaxDynamicSharedMemorySize, kSmemB);
    cudaFuncSetAttribute(gemm_h<1>, cudaFuncAttributeMaxDynamicSharedMemorySize, kSmemB);
    cudaFuncSetAttribute(gemm_h<2>, cudaFuncAttributeMaxDynamicSharedMemorySize, kSmemB);
    cudaFuncSetAttribute(gemm_h<3>, cudaFuncAttributeMaxDynamicSharedMemorySize, kSmemB);

    const float scale = 0.044194173824159216f;  // 512^-0.5

    convert_w_kernel<<<256, 256>>>(qkv_w, proj_w);
    groupnorm_kernel<<<kB * kG, 256>>>(x, gamma, beta, hnt);

    const size_t sHnt = (size_t)kHW * kC;
    const size_t sQkt = (size_t)kHW * 1024;
    const size_t sV   = (size_t)kC * kHW;
    const size_t sE   = (size_t)kHW * kHW;
    const size_t sAtt = (size_t)kHW * kC;
    const size_t sOut = (size_t)kC * kHW;

    // qk^T[p,o] = sum_c hn^T[p,c] * Wqk[o,c] + qkv_b[o]
    gemm_h<1><<<dim3(8, 32, kB), 256, kSmemB>>>(
        hnt, w16_qk, qkt, kHW, 1024, kC, kC, kC, 1024,
        sHnt, 0, sQkt, nullptr, qkv_b, 1.f, nullptr, 0, nullptr);

    // v[c',p] = sum_c Wv[c',c] * hn^T[p,c] + qkv_b[1024+c']
    gemm_h<1><<<dim3(32, 4, kB), 256, kSmemB>>>(
        w16_v, hnt, v, kC, kHW, kC, kC, kC, kHW,
        0, sHnt, sV, qkv_b + 1024, nullptr, 1.f, nullptr, 0, nullptr);

    // E[i,j] = exp(scale * sum_c q^T[i,c] * k^T[j,c]);  rowsum[i] += row partials
    gemm_h<2><<<dim3(32, 32, kB), 256, kSmemB>>>(
        qkt, qkt + 512, E, kHW, kHW, kC, 1024, 1024, kHW,
        sQkt, sQkt, sE, nullptr, nullptr, scale, nullptr, 0, rowsum);

    // att^T[i,c'] = (sum_j E[i,j] * v[c',j]) / rowsum[i]
    gemm_h<3><<<dim3(4, 32, kB), 256, kSmemB>>>(
        E, v, attt, kHW, kC, kHW, kHW, kHW, kC,
        sE, sV, sAtt, nullptr, nullptr, 1.f, nullptr, 0, rowsum);

    // out[o,p] = sum_c Pw[o,c] * att^T[p,c] + proj_b[o] + x[o,p]
    gemm_h<0><<<dim3(32, 4, kB), 256, kSmemB>>>(
        w16_proj, attt, out, kC, kHW, kC, kC, kC, kHW,
        0, sAtt, sOut, proj_b, nullptr, 1.f, x, sOut, nullptr);
}